// round 2
// baseline (speedup 1.0000x reference)
#include <cuda_runtime.h>
#include <math.h>

// Problem dims (fixed)
#define BB   2
#define LL   2048
#define DDIM 1024
#define HH   16
#define DHD  64
#define DFFN 4096
#define MROWS (BB*LL)   // 4096 token rows

// ---------------------------------------------------------------------------
// Scratch (device globals; no runtime allocation allowed)
// ---------------------------------------------------------------------------
__device__ float g_h  [(size_t)MROWS * DDIM];   // LN output (reused for both LNs)
__device__ float g_q  [(size_t)MROWS * DDIM];
__device__ float g_k  [(size_t)MROWS * DDIM];
__device__ float g_v  [(size_t)MROWS * DDIM];
__device__ float g_ctx[(size_t)MROWS * DDIM];
__device__ float g_x1 [(size_t)MROWS * DDIM];   // after first residual
__device__ float g_f  [(size_t)MROWS * DFFN];   // FFN hidden

// ---------------------------------------------------------------------------
// LayerNorm: one block per row, 256 threads, float4 per thread (D=1024)
// ---------------------------------------------------------------------------
__global__ void __launch_bounds__(256) ln_kernel(const float* __restrict__ x,
                                                 const float* __restrict__ g,
                                                 const float* __restrict__ b,
                                                 float* __restrict__ out) {
    int row = blockIdx.x;
    int t = threadIdx.x;
    const float4* xr = (const float4*)(x + (size_t)row * DDIM);
    float4 v = xr[t];
    __shared__ float sred[8];

    float s = v.x + v.y + v.z + v.w;
    #pragma unroll
    for (int o = 16; o > 0; o >>= 1) s += __shfl_xor_sync(0xffffffffu, s, o);
    if ((t & 31) == 0) sred[t >> 5] = s;
    __syncthreads();
    float tot = 0.f;
    #pragma unroll
    for (int w = 0; w < 8; w++) tot += sred[w];
    float mu = tot * (1.0f / DDIM);

    float dx = v.x - mu, dy = v.y - mu, dz = v.z - mu, dw = v.w - mu;
    float s2 = dx*dx + dy*dy + dz*dz + dw*dw;
    #pragma unroll
    for (int o = 16; o > 0; o >>= 1) s2 += __shfl_xor_sync(0xffffffffu, s2, o);
    __syncthreads();               // protect sred reads above
    if ((t & 31) == 0) sred[t >> 5] = s2;
    __syncthreads();
    float tv = 0.f;
    #pragma unroll
    for (int w = 0; w < 8; w++) tv += sred[w];
    float rstd = rsqrtf(tv * (1.0f / DDIM) + 1e-5f);

    float4 gg = ((const float4*)g)[t];
    float4 bb = ((const float4*)b)[t];
    float4 o4;
    o4.x = dx * rstd * gg.x + bb.x;
    o4.y = dy * rstd * gg.y + bb.y;
    o4.z = dz * rstd * gg.z + bb.z;
    o4.w = dw * rstd * gg.w + bb.w;
    ((float4*)(out + (size_t)row * DDIM))[t] = o4;
}

// ---------------------------------------------------------------------------
// Generic fp32 SGEMM: C[M,N] = A[M,K] @ (TB ? B[N,K]^T : B[K,N])
//   epilogue: (+bias[n]) -> (gelu) -> (+res[m,n])
// 64x64x16 tile, 256 threads, 4x4 micro-tile, vectorized smem reads.
// Requires M%64==0, N%64==0, K%16==0 (true for all calls here).
// ---------------------------------------------------------------------------
template<bool TB, bool GELU, bool BIAS, bool RES>
__global__ void __launch_bounds__(256) gemm_kernel(
    const float* __restrict__ A, const float* __restrict__ Bm,
    const float* __restrict__ bias, const float* __restrict__ res,
    float* __restrict__ C, int M, int N, int K) {
    __shared__ float As[16][68];   // [k][m], padded
    __shared__ float Bs[16][68];   // [k][n], padded

    int tid = threadIdx.x;
    int tx = tid & 15, ty = tid >> 4;
    int m0 = blockIdx.y * 64, n0 = blockIdx.x * 64;

    float acc[4][4] = {};

    // A-load mapping: each thread loads a float4 along K
    int ea = tid * 4;
    int am = ea >> 4;      // 0..63
    int ak = ea & 15;      // 0,4,8,12

    for (int k0 = 0; k0 < K; k0 += 16) {
        {
            float4 av = *(const float4*)(A + (size_t)(m0 + am) * K + k0 + ak);
            As[ak + 0][am] = av.x; As[ak + 1][am] = av.y;
            As[ak + 2][am] = av.z; As[ak + 3][am] = av.w;
        }
        if (TB) {
            float4 bv = *(const float4*)(Bm + (size_t)(n0 + am) * K + k0 + ak);
            Bs[ak + 0][am] = bv.x; Bs[ak + 1][am] = bv.y;
            Bs[ak + 2][am] = bv.z; Bs[ak + 3][am] = bv.w;
        } else {
            int bk = tid >> 4;          // 0..15
            int bn = (tid & 15) * 4;    // 0..60
            float4 bv = *(const float4*)(Bm + (size_t)(k0 + bk) * N + n0 + bn);
            *(float4*)&Bs[bk][bn] = bv;
        }
        __syncthreads();
        #pragma unroll
        for (int kk = 0; kk < 16; kk++) {
            float4 a4 = *(const float4*)&As[kk][ty * 4];
            float4 b4 = *(const float4*)&Bs[kk][tx * 4];
            float av[4] = {a4.x, a4.y, a4.z, a4.w};
            float bw[4] = {b4.x, b4.y, b4.z, b4.w};
            #pragma unroll
            for (int i = 0; i < 4; i++)
                #pragma unroll
                for (int j = 0; j < 4; j++)
                    acc[i][j] += av[i] * bw[j];
        }
        __syncthreads();
    }

    #pragma unroll
    for (int i = 0; i < 4; i++) {
        int m = m0 + ty * 4 + i;
        #pragma unroll
        for (int j = 0; j < 4; j++) {
            int n = n0 + tx * 4 + j;
            float vv = acc[i][j];
            if (BIAS) vv += bias[n];
            if (GELU) vv = 0.5f * vv * (1.0f + erff(vv * 0.70710678118654752f));
            if (RES)  vv += res[(size_t)m * N + n];
            C[(size_t)m * N + n] = vv;
        }
    }
}

// ---------------------------------------------------------------------------
// Causal flash attention, fp32. One block per (q-tile of 64 rows, b*h).
// BM=64 q rows, BN=32 k cols per inner tile, DH=64. Online softmax.
// Thread layout 16x16: ty -> 4 q rows, tx -> 2 k cols (S) / 4 dv cols (O).
// ---------------------------------------------------------------------------
__global__ void __launch_bounds__(256) attn_kernel(
    const float* __restrict__ Q, const float* __restrict__ K,
    const float* __restrict__ V, float* __restrict__ O) {
    __shared__ float Qs[64][68];   // [d][r]
    __shared__ float Ks[64][36];   // [d][c]
    __shared__ float Vs[32][68];   // [c][d]
    __shared__ float Ps[64][36];   // [r][c]

    int tid = threadIdx.x;
    int tx = tid & 15, ty = tid >> 4;
    int qt = blockIdx.x;
    int bh = blockIdx.y;
    size_t base = (size_t)(bh / HH) * LL * DDIM + (size_t)(bh % HH) * DHD;
    int q0 = qt * 64;

    for (int e = tid; e < 64 * 64; e += 256) {
        int r = e >> 6, d = e & 63;
        Qs[d][r] = Q[base + (size_t)(q0 + r) * DDIM + d];
    }

    float o[4][4] = {};
    float mrow[4], lrow[4];
    #pragma unroll
    for (int i = 0; i < 4; i++) { mrow[i] = -3.0e38f; lrow[i] = 0.f; }
    __syncthreads();

    int nkt = (q0 + 64) / 32;      // causal: only k-tiles up to the diagonal
    for (int kt = 0; kt < nkt; kt++) {
        int k0 = kt * 32;
        for (int e = tid; e < 32 * 64; e += 256) {
            int c = e >> 6, d = e & 63;
            float kv = K[base + (size_t)(k0 + c) * DDIM + d];
            float vv = V[base + (size_t)(k0 + c) * DDIM + d];
            Ks[d][c] = kv;
            Vs[c][d] = vv;
        }
        __syncthreads();

        // S = Q @ K^T (64x32 tile), micro 4x2
        float s[4][2] = {};
        #pragma unroll 16
        for (int d = 0; d < 64; d++) {
            float4 a4 = *(const float4*)&Qs[d][ty * 4];
            float2 b2 = *(const float2*)&Ks[d][tx * 2];
            float av[4] = {a4.x, a4.y, a4.z, a4.w};
            float bw[2] = {b2.x, b2.y};
            #pragma unroll
            for (int i = 0; i < 4; i++)
                #pragma unroll
                for (int j = 0; j < 2; j++)
                    s[i][j] += av[i] * bw[j];
        }

        bool need_mask = (k0 + 31 > q0);
        #pragma unroll
        for (int i = 0; i < 4; i++)
            #pragma unroll
            for (int j = 0; j < 2; j++) {
                s[i][j] *= 0.125f;   // 1/sqrt(64)
                if (need_mask && (k0 + tx * 2 + j > q0 + ty * 4 + i))
                    s[i][j] = -3.0e38f;
            }

        // per-row max across the 16 tx lanes (lanes 0..15 / 16..31 of a warp)
        float tmax[4];
        #pragma unroll
        for (int i = 0; i < 4; i++) tmax[i] = fmaxf(s[i][0], s[i][1]);
        #pragma unroll
        for (int off = 8; off > 0; off >>= 1)
            #pragma unroll
            for (int i = 0; i < 4; i++)
                tmax[i] = fmaxf(tmax[i], __shfl_xor_sync(0xffffffffu, tmax[i], off));

        float fc[4];
        #pragma unroll
        for (int i = 0; i < 4; i++) {
            float mn = fmaxf(mrow[i], tmax[i]);
            fc[i] = __expf(mrow[i] - mn);
            mrow[i] = mn;
        }

        float p[4][2], tsum[4];
        #pragma unroll
        for (int i = 0; i < 4; i++) {
            tsum[i] = 0.f;
            #pragma unroll
            for (int j = 0; j < 2; j++) {
                p[i][j] = __expf(s[i][j] - mrow[i]);
                tsum[i] += p[i][j];
            }
        }
        #pragma unroll
        for (int off = 8; off > 0; off >>= 1)
            #pragma unroll
            for (int i = 0; i < 4; i++)
                tsum[i] += __shfl_xor_sync(0xffffffffu, tsum[i], off);

        #pragma unroll
        for (int i = 0; i < 4; i++) {
            lrow[i] = lrow[i] * fc[i] + tsum[i];
            #pragma unroll
            for (int j = 0; j < 4; j++) o[i][j] *= fc[i];
        }

        #pragma unroll
        for (int i = 0; i < 4; i++)
            #pragma unroll
            for (int j = 0; j < 2; j++)
                Ps[ty * 4 + i][tx * 2 + j] = p[i][j];
        __syncthreads();

        // O += P @ V (64x64), micro 4x4, inner over 32 k cols
        #pragma unroll
        for (int c4 = 0; c4 < 32; c4 += 4) {
            float par[4][4];
            #pragma unroll
            for (int i = 0; i < 4; i++) {
                float4 t4 = *(const float4*)&Ps[ty * 4 + i][c4];
                par[i][0] = t4.x; par[i][1] = t4.y; par[i][2] = t4.z; par[i][3] = t4.w;
            }
            #pragma unroll
            for (int cc = 0; cc < 4; cc++) {
                float4 bv = *(const float4*)&Vs[c4 + cc][tx * 4];
                float bvr[4] = {bv.x, bv.y, bv.z, bv.w};
                #pragma unroll
                for (int i = 0; i < 4; i++)
                    #pragma unroll
                    for (int j = 0; j < 4; j++)
                        o[i][j] += par[i][cc] * bvr[j];
            }
        }
        __syncthreads();
    }

    #pragma unroll
    for (int i = 0; i < 4; i++) {
        float inv = 1.0f / lrow[i];
        #pragma unroll
        for (int j = 0; j < 4; j++)
            O[base + (size_t)(q0 + ty * 4 + i) * DDIM + tx * 4 + j] = o[i][j] * inv;
    }
}

// ---------------------------------------------------------------------------
// Launch sequence
// ---------------------------------------------------------------------------
extern "C" void kernel_launch(void* const* d_in, const int* in_sizes, int n_in,
                              void* d_out, int out_size) {
    const float* x     = (const float*)d_in[0];
    // d_in[1] = attn_mask: exactly the causal -inf mask; applied analytically.
    const float* ln1_g = (const float*)d_in[2];
    const float* ln1_b = (const float*)d_in[3];
    const float* W_q   = (const float*)d_in[4];
    const float* W_k   = (const float*)d_in[5];
    const float* W_v   = (const float*)d_in[6];
    const float* W_o   = (const float*)d_in[7];
    const float* ln2_g = (const float*)d_in[8];
    const float* ln2_b = (const float*)d_in[9];
    const float* fc1_W = (const float*)d_in[10];
    const float* fc1_b = (const float*)d_in[11];
    const float* fc2_W = (const float*)d_in[12];
    const float* fc2_b = (const float*)d_in[13];
    float* out = (float*)d_out;

    float *h, *q, *k, *v, *ctx, *x1, *f;
    cudaGetSymbolAddress((void**)&h,   g_h);
    cudaGetSymbolAddress((void**)&q,   g_q);
    cudaGetSymbolAddress((void**)&k,   g_k);
    cudaGetSymbolAddress((void**)&v,   g_v);
    cudaGetSymbolAddress((void**)&ctx, g_ctx);
    cudaGetSymbolAddress((void**)&x1,  g_x1);
    cudaGetSymbolAddress((void**)&f,   g_f);

    dim3 gDD(DDIM / 64, MROWS / 64);       // [4096 x 1024] GEMMs
    dim3 gFF(DFFN / 64, MROWS / 64);       // [4096 x 4096] GEMM

    // 1) h = LN1(x)
    ln_kernel<<<MROWS, 256>>>(x, ln1_g, ln1_b, h);
    // 2) q,k,v = h @ W^T  (NT)
    gemm_kernel<true , false, false, false><<<gDD, 256>>>(h, W_q, nullptr, nullptr, q, MROWS, DDIM, DDIM);
    gemm_kernel<true , false, false, false><<<gDD, 256>>>(h, W_k, nullptr, nullptr, k, MROWS, DDIM, DDIM);
    gemm_kernel<true , false, false, false><<<gDD, 256>>>(h, W_v, nullptr, nullptr, v, MROWS, DDIM, DDIM);
    // 3) ctx = causal-softmax(q k^T / 8) v   per (b,h)
    attn_kernel<<<dim3(LL / 64, BB * HH), 256>>>(q, k, v, ctx);
    // 4) x1 = x + ctx @ W_o^T  (NT + residual)
    gemm_kernel<true , false, false, true ><<<gDD, 256>>>(ctx, W_o, nullptr, x, x1, MROWS, DDIM, DDIM);
    // 5) h = LN2(x1)
    ln_kernel<<<MROWS, 256>>>(x1, ln2_g, ln2_b, h);
    // 6) f = gelu(h @ fc1_W + fc1_b)  (NN + bias + gelu)
    gemm_kernel<false, true , true , false><<<gFF, 256>>>(h, fc1_W, fc1_b, nullptr, f, MROWS, DFFN, DDIM);
    // 7) out = x1 + f @ fc2_W + fc2_b  (NN + bias + residual)
    gemm_kernel<false, false, true , true ><<<gDD, 256>>>(f, fc2_W, fc2_b, x1, out, MROWS, DDIM, DFFN);
}

// round 3
// speedup vs baseline: 2.1389x; 2.1389x over previous
#include <cuda_runtime.h>
#include <math.h>
#include <stdint.h>

// Problem dims (fixed)
#define BB   2
#define LL   2048
#define DDIM 1024
#define HH   16
#define DHD  64
#define DFFN 4096
#define MROWS (BB*LL)   // 4096 token rows

// ---------------------------------------------------------------------------
// Scratch (device globals; no runtime allocation allowed)
// ---------------------------------------------------------------------------
__device__ float g_h  [(size_t)MROWS * DDIM];
__device__ float g_q  [(size_t)MROWS * DDIM];
__device__ float g_k  [(size_t)MROWS * DDIM];
__device__ float g_v  [(size_t)MROWS * DDIM];
__device__ float g_ctx[(size_t)MROWS * DDIM];
__device__ float g_x1 [(size_t)MROWS * DDIM];
__device__ float g_f  [(size_t)MROWS * DFFN];

// ---------------------------------------------------------------------------
// Small PTX helpers
// ---------------------------------------------------------------------------
__device__ __forceinline__ uint32_t smem_u32(const void* p) {
    return (uint32_t)__cvta_generic_to_shared(p);
}
__device__ __forceinline__ void cp_async16(uint32_t dst, const void* src) {
    asm volatile("cp.async.cg.shared.global [%0], [%1], 16;" :: "r"(dst), "l"(src));
}
__device__ __forceinline__ void cp_commit() {
    asm volatile("cp.async.commit_group;");
}
template<int N>
__device__ __forceinline__ void cp_wait() {
    asm volatile("cp.async.wait_group %0;" :: "n"(N));
}
__device__ __forceinline__ uint32_t to_tf32(float f) {
    uint32_t r;
    asm("cvt.rna.tf32.f32 %0, %1;" : "=r"(r) : "f"(f));
    return r;
}
__device__ __forceinline__ void mma_tf32(float* c, const uint32_t* a, const uint32_t* b) {
    asm volatile(
        "mma.sync.aligned.m16n8k8.row.col.f32.tf32.tf32.f32 "
        "{%0,%1,%2,%3},{%4,%5,%6,%7},{%8,%9},{%0,%1,%2,%3};"
        : "+f"(c[0]), "+f"(c[1]), "+f"(c[2]), "+f"(c[3])
        : "r"(a[0]), "r"(a[1]), "r"(a[2]), "r"(a[3]), "r"(b[0]), "r"(b[1]));
}

// ---------------------------------------------------------------------------
// LayerNorm (unchanged; passed correctness)
// ---------------------------------------------------------------------------
__global__ void __launch_bounds__(256) ln_kernel(const float* __restrict__ x,
                                                 const float* __restrict__ g,
                                                 const float* __restrict__ b,
                                                 float* __restrict__ out) {
    int row = blockIdx.x;
    int t = threadIdx.x;
    const float4* xr = (const float4*)(x + (size_t)row * DDIM);
    float4 v = xr[t];
    __shared__ float sred[8];

    float s = v.x + v.y + v.z + v.w;
    #pragma unroll
    for (int o = 16; o > 0; o >>= 1) s += __shfl_xor_sync(0xffffffffu, s, o);
    if ((t & 31) == 0) sred[t >> 5] = s;
    __syncthreads();
    float tot = 0.f;
    #pragma unroll
    for (int w = 0; w < 8; w++) tot += sred[w];
    float mu = tot * (1.0f / DDIM);

    float dx = v.x - mu, dy = v.y - mu, dz = v.z - mu, dw = v.w - mu;
    float s2 = dx*dx + dy*dy + dz*dz + dw*dw;
    #pragma unroll
    for (int o = 16; o > 0; o >>= 1) s2 += __shfl_xor_sync(0xffffffffu, s2, o);
    __syncthreads();
    if ((t & 31) == 0) sred[t >> 5] = s2;
    __syncthreads();
    float tv = 0.f;
    #pragma unroll
    for (int w = 0; w < 8; w++) tv += sred[w];
    float rstd = rsqrtf(tv * (1.0f / DDIM) + 1e-5f);

    float4 gg = ((const float4*)g)[t];
    float4 bb = ((const float4*)b)[t];
    float4 o4;
    o4.x = dx * rstd * gg.x + bb.x;
    o4.y = dy * rstd * gg.y + bb.y;
    o4.z = dz * rstd * gg.z + bb.z;
    o4.w = dw * rstd * gg.w + bb.w;
    ((float4*)(out + (size_t)row * DDIM))[t] = o4;
}

// ---------------------------------------------------------------------------
// tf32 tensor-core GEMM: C[M,N] = A[M,K] @ (TB ? B[N,K]^T : B[K,N])
//   epilogue: (+bias[n]) -> (gelu) -> (+res[m,n])
// CTA tile 128x128x16, 256 threads (8 warps, 2x4), warp tile 64x32,
// mma.m16n8k8.tf32, cp.async double buffering.
// smem strides chosen conflict-free for fragment LDS:
//   A / B(NT): [row][k] stride 20  -> row*20 mod 32 in {0,20,8,28,16,4,24,12}
//   B(NN):     [k][n]  stride 136 -> k*136 mod 32 = k*8 -> k*8+n covers 0..31
// ---------------------------------------------------------------------------
#define BMT 128
#define BNT 128
#define BKT 16

template<bool TB, bool GELU, bool BIAS, bool RES>
__global__ void __launch_bounds__(256) gemm_tc(
    const float* __restrict__ A, const float* __restrict__ Bm,
    const float* __restrict__ bias, const float* __restrict__ res,
    float* __restrict__ C, int M, int N, int K)
{
    __shared__ float As[2][BMT * 20];      // [row][k], stride 20
    __shared__ float Bs[2][2560];          // NT: [n][k] stride 20; NN: [k][n] stride 136

    int tid  = threadIdx.x;
    int lane = tid & 31;
    int wid  = tid >> 5;
    int wm   = wid >> 2;     // 0..1  (64 rows)
    int wn   = wid & 3;      // 0..3  (32 cols)
    int m0 = blockIdx.y * BMT;
    int n0 = blockIdx.x * BNT;

    float acc[4][4][4];
    #pragma unroll
    for (int i = 0; i < 4; i++)
        #pragma unroll
        for (int j = 0; j < 4; j++)
            #pragma unroll
            for (int r = 0; r < 4; r++) acc[i][j][r] = 0.f;

    // ---- async tile loader ----
    auto issue = [&](int buf, int k0) {
        // A: 128 rows x 16 floats = 512 x 16B, 2 per thread
        #pragma unroll
        for (int i = 0; i < 2; i++) {
            int idx = tid + i * 256;
            int row = idx >> 2, c = idx & 3;
            cp_async16(smem_u32(&As[buf][row * 20 + c * 4]),
                       A + (size_t)(m0 + row) * K + k0 + c * 4);
        }
        if (TB) {
            #pragma unroll
            for (int i = 0; i < 2; i++) {
                int idx = tid + i * 256;
                int row = idx >> 2, c = idx & 3;
                cp_async16(smem_u32(&Bs[buf][row * 20 + c * 4]),
                           Bm + (size_t)(n0 + row) * K + k0 + c * 4);
            }
        } else {
            #pragma unroll
            for (int i = 0; i < 2; i++) {
                int idx = tid + i * 256;
                int k = idx >> 5, n4 = idx & 31;
                cp_async16(smem_u32(&Bs[buf][k * 136 + n4 * 4]),
                           Bm + (size_t)(k0 + k) * N + n0 + n4 * 4);
            }
        }
    };

    int nk = K / BKT;
    issue(0, 0);
    cp_commit();

    int buf = 0;
    for (int kt = 0; kt < nk; kt++) {
        __syncthreads();             // prev compute done before overwriting buf^1
        if (kt + 1 < nk) {
            issue(buf ^ 1, (kt + 1) * BKT);
            cp_commit();
            cp_wait<1>();            // current buf's group complete
        } else {
            cp_wait<0>();
        }
        __syncthreads();

        #pragma unroll
        for (int ks = 0; ks < 2; ks++) {
            uint32_t af[4][4], bf[4][2];
            int ar = wm * 64 + (lane >> 2);
            int ak = ks * 8 + (lane & 3);
            #pragma unroll
            for (int mt = 0; mt < 4; mt++) {
                int r = ar + mt * 16;
                af[mt][0] = to_tf32(As[buf][ r      * 20 + ak    ]);
                af[mt][1] = to_tf32(As[buf][(r + 8) * 20 + ak    ]);
                af[mt][2] = to_tf32(As[buf][ r      * 20 + ak + 4]);
                af[mt][3] = to_tf32(As[buf][(r + 8) * 20 + ak + 4]);
            }
            #pragma unroll
            for (int nt = 0; nt < 4; nt++) {
                int bn = wn * 32 + nt * 8 + (lane >> 2);
                if (TB) {
                    bf[nt][0] = to_tf32(Bs[buf][bn * 20 + ak    ]);
                    bf[nt][1] = to_tf32(Bs[buf][bn * 20 + ak + 4]);
                } else {
                    bf[nt][0] = to_tf32(Bs[buf][(ak    ) * 136 + bn]);
                    bf[nt][1] = to_tf32(Bs[buf][(ak + 4) * 136 + bn]);
                }
            }
            #pragma unroll
            for (int mt = 0; mt < 4; mt++)
                #pragma unroll
                for (int nt = 0; nt < 4; nt++)
                    mma_tf32(acc[mt][nt], af[mt], bf[nt]);
        }
        buf ^= 1;
    }

    // ---- epilogue ----
    #pragma unroll
    for (int mt = 0; mt < 4; mt++) {
        #pragma unroll
        for (int nt = 0; nt < 4; nt++) {
            int row = m0 + wm * 64 + mt * 16 + (lane >> 2);
            int col = n0 + wn * 32 + nt * 8 + (lane & 3) * 2;
            #pragma unroll
            for (int half = 0; half < 2; half++) {
                int r = row + half * 8;
                float v0 = acc[mt][nt][half * 2 + 0];
                float v1 = acc[mt][nt][half * 2 + 1];
                if (BIAS) { v0 += bias[col]; v1 += bias[col + 1]; }
                if (GELU) {
                    v0 = 0.5f * v0 * (1.0f + erff(v0 * 0.70710678118654752f));
                    v1 = 0.5f * v1 * (1.0f + erff(v1 * 0.70710678118654752f));
                }
                if (RES) {
                    const float2 rr = *(const float2*)(res + (size_t)r * N + col);
                    v0 += rr.x; v1 += rr.y;
                }
                float2 o2; o2.x = v0; o2.y = v1;
                *(float2*)(C + (size_t)r * N + col) = o2;
            }
        }
    }
}

// ---------------------------------------------------------------------------
// Causal flash attention, fp32 (unchanged; passed correctness)
// ---------------------------------------------------------------------------
__global__ void __launch_bounds__(256) attn_kernel(
    const float* __restrict__ Q, const float* __restrict__ K,
    const float* __restrict__ V, float* __restrict__ O) {
    __shared__ float Qs[64][68];
    __shared__ float Ks[64][36];
    __shared__ float Vs[32][68];
    __shared__ float Ps[64][36];

    int tid = threadIdx.x;
    int tx = tid & 15, ty = tid >> 4;
    int qt = blockIdx.x;
    int bh = blockIdx.y;
    size_t base = (size_t)(bh / HH) * LL * DDIM + (size_t)(bh % HH) * DHD;
    int q0 = qt * 64;

    for (int e = tid; e < 64 * 64; e += 256) {
        int r = e >> 6, d = e & 63;
        Qs[d][r] = Q[base + (size_t)(q0 + r) * DDIM + d];
    }

    float o[4][4] = {};
    float mrow[4], lrow[4];
    #pragma unroll
    for (int i = 0; i < 4; i++) { mrow[i] = -3.0e38f; lrow[i] = 0.f; }
    __syncthreads();

    int nkt = (q0 + 64) / 32;
    for (int kt = 0; kt < nkt; kt++) {
        int k0 = kt * 32;
        for (int e = tid; e < 32 * 64; e += 256) {
            int c = e >> 6, d = e & 63;
            Ks[d][c] = K[base + (size_t)(k0 + c) * DDIM + d];
            Vs[c][d] = V[base + (size_t)(k0 + c) * DDIM + d];
        }
        __syncthreads();

        float s[4][2] = {};
        #pragma unroll 16
        for (int d = 0; d < 64; d++) {
            float4 a4 = *(const float4*)&Qs[d][ty * 4];
            float2 b2 = *(const float2*)&Ks[d][tx * 2];
            float av[4] = {a4.x, a4.y, a4.z, a4.w};
            float bw[2] = {b2.x, b2.y};
            #pragma unroll
            for (int i = 0; i < 4; i++)
                #pragma unroll
                for (int j = 0; j < 2; j++)
                    s[i][j] += av[i] * bw[j];
        }

        bool need_mask = (k0 + 31 > q0);
        #pragma unroll
        for (int i = 0; i < 4; i++)
            #pragma unroll
            for (int j = 0; j < 2; j++) {
                s[i][j] *= 0.125f;
                if (need_mask && (k0 + tx * 2 + j > q0 + ty * 4 + i))
                    s[i][j] = -3.0e38f;
            }

        float tmax[4];
        #pragma unroll
        for (int i = 0; i < 4; i++) tmax[i] = fmaxf(s[i][0], s[i][1]);
        #pragma unroll
        for (int off = 8; off > 0; off >>= 1)
            #pragma unroll
            for (int i = 0; i < 4; i++)
                tmax[i] = fmaxf(tmax[i], __shfl_xor_sync(0xffffffffu, tmax[i], off));

        float fc[4];
        #pragma unroll
        for (int i = 0; i < 4; i++) {
            float mn = fmaxf(mrow[i], tmax[i]);
            fc[i] = __expf(mrow[i] - mn);
            mrow[i] = mn;
        }

        float p[4][2], tsum[4];
        #pragma unroll
        for (int i = 0; i < 4; i++) {
            tsum[i] = 0.f;
            #pragma unroll
            for (int j = 0; j < 2; j++) {
                p[i][j] = __expf(s[i][j] - mrow[i]);
                tsum[i] += p[i][j];
            }
        }
        #pragma unroll
        for (int off = 8; off > 0; off >>= 1)
            #pragma unroll
            for (int i = 0; i < 4; i++)
                tsum[i] += __shfl_xor_sync(0xffffffffu, tsum[i], off);

        #pragma unroll
        for (int i = 0; i < 4; i++) {
            lrow[i] = lrow[i] * fc[i] + tsum[i];
            #pragma unroll
            for (int j = 0; j < 4; j++) o[i][j] *= fc[i];
        }

        #pragma unroll
        for (int i = 0; i < 4; i++)
            #pragma unroll
            for (int j = 0; j < 2; j++)
                Ps[ty * 4 + i][tx * 2 + j] = p[i][j];
        __syncthreads();

        #pragma unroll
        for (int c4 = 0; c4 < 32; c4 += 4) {
            float par[4][4];
            #pragma unroll
            for (int i = 0; i < 4; i++) {
                float4 t4 = *(const float4*)&Ps[ty * 4 + i][c4];
                par[i][0] = t4.x; par[i][1] = t4.y; par[i][2] = t4.z; par[i][3] = t4.w;
            }
            #pragma unroll
            for (int cc = 0; cc < 4; cc++) {
                float4 bv = *(const float4*)&Vs[c4 + cc][tx * 4];
                float bvr[4] = {bv.x, bv.y, bv.z, bv.w};
                #pragma unroll
                for (int i = 0; i < 4; i++)
                    #pragma unroll
                    for (int j = 0; j < 4; j++)
                        o[i][j] += par[i][cc] * bvr[j];
            }
        }
        __syncthreads();
    }

    #pragma unroll
    for (int i = 0; i < 4; i++) {
        float inv = 1.0f / lrow[i];
        #pragma unroll
        for (int j = 0; j < 4; j++)
            O[base + (size_t)(q0 + ty * 4 + i) * DDIM + tx * 4 + j] = o[i][j] * inv;
    }
}

// ---------------------------------------------------------------------------
// Launch sequence
// ---------------------------------------------------------------------------
extern "C" void kernel_launch(void* const* d_in, const int* in_sizes, int n_in,
                              void* d_out, int out_size) {
    const float* x     = (const float*)d_in[0];
    const float* ln1_g = (const float*)d_in[2];
    const float* ln1_b = (const float*)d_in[3];
    const float* W_q   = (const float*)d_in[4];
    const float* W_k   = (const float*)d_in[5];
    const float* W_v   = (const float*)d_in[6];
    const float* W_o   = (const float*)d_in[7];
    const float* ln2_g = (const float*)d_in[8];
    const float* ln2_b = (const float*)d_in[9];
    const float* fc1_W = (const float*)d_in[10];
    const float* fc1_b = (const float*)d_in[11];
    const float* fc2_W = (const float*)d_in[12];
    const float* fc2_b = (const float*)d_in[13];
    float* out = (float*)d_out;

    float *h, *q, *k, *v, *ctx, *x1, *f;
    cudaGetSymbolAddress((void**)&h,   g_h);
    cudaGetSymbolAddress((void**)&q,   g_q);
    cudaGetSymbolAddress((void**)&k,   g_k);
    cudaGetSymbolAddress((void**)&v,   g_v);
    cudaGetSymbolAddress((void**)&ctx, g_ctx);
    cudaGetSymbolAddress((void**)&x1,  g_x1);
    cudaGetSymbolAddress((void**)&f,   g_f);

    dim3 gDD(DDIM / BNT, MROWS / BMT);     // (8, 32)
    dim3 gFF(DFFN / BNT, MROWS / BMT);     // (32, 32)

    ln_kernel<<<MROWS, 256>>>(x, ln1_g, ln1_b, h);
    gemm_tc<true , false, false, false><<<gDD, 256>>>(h, W_q, nullptr, nullptr, q, MROWS, DDIM, DDIM);
    gemm_tc<true , false, false, false><<<gDD, 256>>>(h, W_k, nullptr, nullptr, k, MROWS, DDIM, DDIM);
    gemm_tc<true , false, false, false><<<gDD, 256>>>(h, W_v, nullptr, nullptr, v, MROWS, DDIM, DDIM);
    attn_kernel<<<dim3(LL / 64, BB * HH), 256>>>(q, k, v, ctx);
    gemm_tc<true , false, false, true ><<<gDD, 256>>>(ctx, W_o, nullptr, x, x1, MROWS, DDIM, DDIM);
    ln_kernel<<<MROWS, 256>>>(x1, ln2_g, ln2_b, h);
    gemm_tc<false, true , true , false><<<gFF, 256>>>(h, fc1_W, fc1_b, nullptr, f, MROWS, DFFN, DDIM);
    gemm_tc<false, false, true , true ><<<gDD, 256>>>(f, fc2_W, fc2_b, x1, out, MROWS, DDIM, DFFN);
}

// round 6
// speedup vs baseline: 2.3094x; 1.0797x over previous
#include <cuda_runtime.h>
#include <math.h>
#include <stdint.h>

// Problem dims (fixed)
#define BB   2
#define LL   2048
#define DDIM 1024
#define HH   16
#define DHD  64
#define DFFN 4096
#define MROWS (BB*LL)   // 4096 token rows

// ---------------------------------------------------------------------------
// Scratch (device globals; no runtime allocation allowed)
// ---------------------------------------------------------------------------
__device__ float g_h  [(size_t)MROWS * DDIM];
__device__ float g_q  [(size_t)MROWS * DDIM];
__device__ float g_k  [(size_t)MROWS * DDIM];
__device__ float g_v  [(size_t)MROWS * DDIM];
__device__ float g_ctx[(size_t)MROWS * DDIM];
__device__ float g_x1 [(size_t)MROWS * DDIM];
__device__ float g_f  [(size_t)MROWS * DFFN];

// ---------------------------------------------------------------------------
// Small PTX helpers
// ---------------------------------------------------------------------------
__device__ __forceinline__ uint32_t smem_u32(const void* p) {
    return (uint32_t)__cvta_generic_to_shared(p);
}
__device__ __forceinline__ void cp_async16(uint32_t dst, const void* src) {
    asm volatile("cp.async.cg.shared.global [%0], [%1], 16;" :: "r"(dst), "l"(src));
}
__device__ __forceinline__ void cp_commit() {
    asm volatile("cp.async.commit_group;");
}
template<int N>
__device__ __forceinline__ void cp_wait() {
    asm volatile("cp.async.wait_group %0;" :: "n"(N));
}
// mma tf32: operands are raw fp32 bits (hardware truncates low mantissa; no CVT)
__device__ __forceinline__ void mma_tf32(float* c, const uint32_t* a, const uint32_t* b) {
    asm volatile(
        "mma.sync.aligned.m16n8k8.row.col.f32.tf32.tf32.f32 "
        "{%0,%1,%2,%3},{%4,%5,%6,%7},{%8,%9},{%0,%1,%2,%3};"
        : "+f"(c[0]), "+f"(c[1]), "+f"(c[2]), "+f"(c[3])
        : "r"(a[0]), "r"(a[1]), "r"(a[2]), "r"(a[3]), "r"(b[0]), "r"(b[1]));
}

// ---------------------------------------------------------------------------
// LayerNorm (unchanged; correctness-anchored)
// ---------------------------------------------------------------------------
__global__ void __launch_bounds__(256) ln_kernel(const float* __restrict__ x,
                                                 const float* __restrict__ g,
                                                 const float* __restrict__ b,
                                                 float* __restrict__ out) {
    int row = blockIdx.x;
    int t = threadIdx.x;
    const float4* xr = (const float4*)(x + (size_t)row * DDIM);
    float4 v = xr[t];
    __shared__ float sred[8];

    float s = v.x + v.y + v.z + v.w;
    #pragma unroll
    for (int o = 16; o > 0; o >>= 1) s += __shfl_xor_sync(0xffffffffu, s, o);
    if ((t & 31) == 0) sred[t >> 5] = s;
    __syncthreads();
    float tot = 0.f;
    #pragma unroll
    for (int w = 0; w < 8; w++) tot += sred[w];
    float mu = tot * (1.0f / DDIM);

    float dx = v.x - mu, dy = v.y - mu, dz = v.z - mu, dw = v.w - mu;
    float s2 = dx*dx + dy*dy + dz*dz + dw*dw;
    #pragma unroll
    for (int o = 16; o > 0; o >>= 1) s2 += __shfl_xor_sync(0xffffffffu, s2, o);
    __syncthreads();
    if ((t & 31) == 0) sred[t >> 5] = s2;
    __syncthreads();
    float tv = 0.f;
    #pragma unroll
    for (int w = 0; w < 8; w++) tv += sred[w];
    float rstd = rsqrtf(tv * (1.0f / DDIM) + 1e-5f);

    float4 gg = ((const float4*)g)[t];
    float4 bb = ((const float4*)b)[t];
    float4 o4;
    o4.x = dx * rstd * gg.x + bb.x;
    o4.y = dy * rstd * gg.y + bb.y;
    o4.z = dz * rstd * gg.z + bb.z;
    o4.w = dw * rstd * gg.w + bb.w;
    ((float4*)(out + (size_t)row * DDIM))[t] = o4;
}

// ---------------------------------------------------------------------------
// tf32 tensor-core GEMM: C[M,N] = A[M,K] @ (TB ? B[N,K]^T : B[K,N])
// CTA 128x128x16, 8 warps (2x4), warp 64x32, mma.m16n8k8.
// 3-stage cp.async ring, ONE __syncthreads per k-tile.
// No cvt.tf32 — raw fp32 bits fed to MMA (truncation, ~2x rounding error, OK).
// smem per stage: A 128*20, B max(128*20, 16*136)=2560 floats.
// ---------------------------------------------------------------------------
#define BMT 128
#define BNT 128
#define BKT 16
#define NSTG 3
#define STG_F 2560                       // floats per stage per matrix
#define GEMM_SMEM (NSTG * STG_F * 2 * 4) // bytes = 61440

template<bool TB, bool GELU, bool BIAS, bool RES>
__global__ void __launch_bounds__(256) gemm_tc(
    const float* __restrict__ A, const float* __restrict__ Bm,
    const float* __restrict__ bias, const float* __restrict__ res,
    float* __restrict__ C, int M, int N, int K)
{
    extern __shared__ float sm[];
    float* As = sm;                  // [NSTG][2560]  ([row][k] stride 20)
    float* Bs = sm + NSTG * STG_F;   // [NSTG][2560]  (NT: [n][k] s20; NN: [k][n] s136)

    int tid  = threadIdx.x;
    int lane = tid & 31;
    int wid  = tid >> 5;
    int wm   = wid >> 2;     // 0..1  (64 rows)
    int wn   = wid & 3;      // 0..3  (32 cols)
    int m0 = blockIdx.y * BMT;
    int n0 = blockIdx.x * BNT;

    float acc[4][4][4];
    #pragma unroll
    for (int i = 0; i < 4; i++)
        #pragma unroll
        for (int j = 0; j < 4; j++)
            #pragma unroll
            for (int r = 0; r < 4; r++) acc[i][j][r] = 0.f;

    auto issue = [&](int st, int k0) {
        float* as = As + st * STG_F;
        float* bs = Bs + st * STG_F;
        #pragma unroll
        for (int i = 0; i < 2; i++) {
            int idx = tid + i * 256;
            int row = idx >> 2, c = idx & 3;
            cp_async16(smem_u32(as + row * 20 + c * 4),
                       A + (size_t)(m0 + row) * K + k0 + c * 4);
        }
        if (TB) {
            #pragma unroll
            for (int i = 0; i < 2; i++) {
                int idx = tid + i * 256;
                int row = idx >> 2, c = idx & 3;
                cp_async16(smem_u32(bs + row * 20 + c * 4),
                           Bm + (size_t)(n0 + row) * K + k0 + c * 4);
            }
        } else {
            #pragma unroll
            for (int i = 0; i < 2; i++) {
                int idx = tid + i * 256;
                int k = idx >> 5, n4 = idx & 31;
                cp_async16(smem_u32(bs + k * 136 + n4 * 4),
                           Bm + (size_t)(k0 + k) * N + n0 + n4 * 4);
            }
        }
        cp_commit();
    };

    int nk = K / BKT;
    issue(0, 0);
    issue(1, BKT);

    for (int kt = 0; kt < nk; kt++) {
        if (kt + 1 < nk) cp_wait<1>(); else cp_wait<0>();
        __syncthreads();   // stage kt visible to all; stage (kt-1)%3 free for reuse

        if (kt + 2 < nk) issue((kt + 2) % NSTG, (kt + 2) * BKT);

        const float* as = As + (kt % NSTG) * STG_F;
        const float* bs = Bs + (kt % NSTG) * STG_F;
        #pragma unroll
        for (int ks = 0; ks < 2; ks++) {
            uint32_t af[4][4], bf[4][2];
            int ar = wm * 64 + (lane >> 2);
            int ak = ks * 8 + (lane & 3);
            #pragma unroll
            for (int mt = 0; mt < 4; mt++) {
                int r = ar + mt * 16;
                af[mt][0] = __float_as_uint(as[ r      * 20 + ak    ]);
                af[mt][1] = __float_as_uint(as[(r + 8) * 20 + ak    ]);
                af[mt][2] = __float_as_uint(as[ r      * 20 + ak + 4]);
                af[mt][3] = __float_as_uint(as[(r + 8) * 20 + ak + 4]);
            }
            #pragma unroll
            for (int nt = 0; nt < 4; nt++) {
                int bn = wn * 32 + nt * 8 + (lane >> 2);
                if (TB) {
                    bf[nt][0] = __float_as_uint(bs[bn * 20 + ak    ]);
                    bf[nt][1] = __float_as_uint(bs[bn * 20 + ak + 4]);
                } else {
                    bf[nt][0] = __float_as_uint(bs[(ak    ) * 136 + bn]);
                    bf[nt][1] = __float_as_uint(bs[(ak + 4) * 136 + bn]);
                }
            }
            #pragma unroll
            for (int mt = 0; mt < 4; mt++)
                #pragma unroll
                for (int nt = 0; nt < 4; nt++)
                    mma_tf32(acc[mt][nt], af[mt], bf[nt]);
        }
    }

    // ---- epilogue ----
    #pragma unroll
    for (int mt = 0; mt < 4; mt++) {
        #pragma unroll
        for (int nt = 0; nt < 4; nt++) {
            int row = m0 + wm * 64 + mt * 16 + (lane >> 2);
            int col = n0 + wn * 32 + nt * 8 + (lane & 3) * 2;
            #pragma unroll
            for (int half = 0; half < 2; half++) {
                int r = row + half * 8;
                float v0 = acc[mt][nt][half * 2 + 0];
                float v1 = acc[mt][nt][half * 2 + 1];
                if (BIAS) { v0 += bias[col]; v1 += bias[col + 1]; }
                if (GELU) {
                    v0 = 0.5f * v0 * (1.0f + erff(v0 * 0.70710678118654752f));
                    v1 = 0.5f * v1 * (1.0f + erff(v1 * 0.70710678118654752f));
                }
                if (RES) {
                    const float2 rr = *(const float2*)(res + (size_t)r * N + col);
                    v0 += rr.x; v1 += rr.y;
                }
                float2 o2; o2.x = v0; o2.y = v1;
                *(float2*)(C + (size_t)r * N + col) = o2;
            }
        }
    }
}

// ---------------------------------------------------------------------------
// Causal flash attention, fp32 (unchanged; correctness-anchored)
// ---------------------------------------------------------------------------
__global__ void __launch_bounds__(256) attn_kernel(
    const float* __restrict__ Q, const float* __restrict__ K,
    const float* __restrict__ V, float* __restrict__ O) {
    __shared__ float Qs[64][68];
    __shared__ float Ks[64][36];
    __shared__ float Vs[32][68];
    __shared__ float Ps[64][36];

    int tid = threadIdx.x;
    int tx = tid & 15, ty = tid >> 4;
    int qt = blockIdx.x;
    int bh = blockIdx.y;
    size_t base = (size_t)(bh / HH) * LL * DDIM + (size_t)(bh % HH) * DHD;
    int q0 = qt * 64;

    for (int e = tid; e < 64 * 64; e += 256) {
        int r = e >> 6, d = e & 63;
        Qs[d][r] = Q[base + (size_t)(q0 + r) * DDIM + d];
    }

    float o[4][4] = {};
    float mrow[4], lrow[4];
    #pragma unroll
    for (int i = 0; i < 4; i++) { mrow[i] = -3.0e38f; lrow[i] = 0.f; }
    __syncthreads();

    int nkt = (q0 + 64) / 32;
    for (int kt = 0; kt < nkt; kt++) {
        int k0 = kt * 32;
        for (int e = tid; e < 32 * 64; e += 256) {
            int c = e >> 6, d = e & 63;
            Ks[d][c] = K[base + (size_t)(k0 + c) * DDIM + d];
            Vs[c][d] = V[base + (size_t)(k0 + c) * DDIM + d];
        }
        __syncthreads();

        float s[4][2] = {};
        #pragma unroll 16
        for (int d = 0; d < 64; d++) {
            float4 a4 = *(const float4*)&Qs[d][ty * 4];
            float2 b2 = *(const float2*)&Ks[d][tx * 2];
            float av[4] = {a4.x, a4.y, a4.z, a4.w};
            float bw[2] = {b2.x, b2.y};
            #pragma unroll
            for (int i = 0; i < 4; i++)
                #pragma unroll
                for (int j = 0; j < 2; j++)
                    s[i][j] += av[i] * bw[j];
        }

        bool need_mask = (k0 + 31 > q0);
        #pragma unroll
        for (int i = 0; i < 4; i++)
            #pragma unroll
            for (int j = 0; j < 2; j++) {
                s[i][j] *= 0.125f;
                if (need_mask && (k0 + tx * 2 + j > q0 + ty * 4 + i))
                    s[i][j] = -3.0e38f;
            }

        float tmax[4];
        #pragma unroll
        for (int i = 0; i < 4; i++) tmax[i] = fmaxf(s[i][0], s[i][1]);
        #pragma unroll
        for (int off = 8; off > 0; off >>= 1)
            #pragma unroll
            for (int i = 0; i < 4; i++)
                tmax[i] = fmaxf(tmax[i], __shfl_xor_sync(0xffffffffu, tmax[i], off));

        float fc[4];
        #pragma unroll
        for (int i = 0; i < 4; i++) {
            float mn = fmaxf(mrow[i], tmax[i]);
            fc[i] = __expf(mrow[i] - mn);
            mrow[i] = mn;
        }

        float p[4][2], tsum[4];
        #pragma unroll
        for (int i = 0; i < 4; i++) {
            tsum[i] = 0.f;
            #pragma unroll
            for (int j = 0; j < 2; j++) {
                p[i][j] = __expf(s[i][j] - mrow[i]);
                tsum[i] += p[i][j];
            }
        }
        #pragma unroll
        for (int off = 8; off > 0; off >>= 1)
            #pragma unroll
            for (int i = 0; i < 4; i++)
                tsum[i] += __shfl_xor_sync(0xffffffffu, tsum[i], off);

        #pragma unroll
        for (int i = 0; i < 4; i++) {
            lrow[i] = lrow[i] * fc[i] + tsum[i];
            #pragma unroll
            for (int j = 0; j < 4; j++) o[i][j] *= fc[i];
        }

        #pragma unroll
        for (int i = 0; i < 4; i++)
            #pragma unroll
            for (int j = 0; j < 2; j++)
                Ps[ty * 4 + i][tx * 2 + j] = p[i][j];
        __syncthreads();

        #pragma unroll
        for (int c4 = 0; c4 < 32; c4 += 4) {
            float par[4][4];
            #pragma unroll
            for (int i = 0; i < 4; i++) {
                float4 t4 = *(const float4*)&Ps[ty * 4 + i][c4];
                par[i][0] = t4.x; par[i][1] = t4.y; par[i][2] = t4.z; par[i][3] = t4.w;
            }
            #pragma unroll
            for (int cc = 0; cc < 4; cc++) {
                float4 bv = *(const float4*)&Vs[c4 + cc][tx * 4];
                float bvr[4] = {bv.x, bv.y, bv.z, bv.w};
                #pragma unroll
                for (int i = 0; i < 4; i++)
                    #pragma unroll
                    for (int j = 0; j < 4; j++)
                        o[i][j] += par[i][cc] * bvr[j];
            }
        }
        __syncthreads();
    }

    #pragma unroll
    for (int i = 0; i < 4; i++) {
        float inv = 1.0f / lrow[i];
        #pragma unroll
        for (int j = 0; j < 4; j++)
            O[base + (size_t)(q0 + ty * 4 + i) * DDIM + tx * 4 + j] = o[i][j] * inv;
    }
}

// ---------------------------------------------------------------------------
// Launch sequence
// ---------------------------------------------------------------------------
extern "C" void kernel_launch(void* const* d_in, const int* in_sizes, int n_in,
                              void* d_out, int out_size) {
    const float* x     = (const float*)d_in[0];
    const float* ln1_g = (const float*)d_in[2];
    const float* ln1_b = (const float*)d_in[3];
    const float* W_q   = (const float*)d_in[4];
    const float* W_k   = (const float*)d_in[5];
    const float* W_v   = (const float*)d_in[6];
    const float* W_o   = (const float*)d_in[7];
    const float* ln2_g = (const float*)d_in[8];
    const float* ln2_b = (const float*)d_in[9];
    const float* fc1_W = (const float*)d_in[10];
    const float* fc1_b = (const float*)d_in[11];
    const float* fc2_W = (const float*)d_in[12];
    const float* fc2_b = (const float*)d_in[13];
    float* out = (float*)d_out;

    float *h, *q, *k, *v, *ctx, *x1, *f;
    cudaGetSymbolAddress((void**)&h,   g_h);
    cudaGetSymbolAddress((void**)&q,   g_q);
    cudaGetSymbolAddress((void**)&k,   g_k);
    cudaGetSymbolAddress((void**)&v,   g_v);
    cudaGetSymbolAddress((void**)&ctx, g_ctx);
    cudaGetSymbolAddress((void**)&x1,  g_x1);
    cudaGetSymbolAddress((void**)&f,   g_f);

    // raise dynamic smem limit (host-side attr; graph-capture safe)
    cudaFuncSetAttribute(gemm_tc<true , false, false, false>, cudaFuncAttributeMaxDynamicSharedMemorySize, GEMM_SMEM);
    cudaFuncSetAttribute(gemm_tc<true , false, false, true >, cudaFuncAttributeMaxDynamicSharedMemorySize, GEMM_SMEM);
    cudaFuncSetAttribute(gemm_tc<false, true , true , false>, cudaFuncAttributeMaxDynamicSharedMemorySize, GEMM_SMEM);
    cudaFuncSetAttribute(gemm_tc<false, false, true , true >, cudaFuncAttributeMaxDynamicSharedMemorySize, GEMM_SMEM);

    dim3 gDD(DDIM / BNT, MROWS / BMT);     // (8, 32)
    dim3 gFF(DFFN / BNT, MROWS / BMT);     // (32, 32)

    ln_kernel<<<MROWS, 256>>>(x, ln1_g, ln1_b, h);
    gemm_tc<true , false, false, false><<<gDD, 256, GEMM_SMEM>>>(h, W_q, nullptr, nullptr, q, MROWS, DDIM, DDIM);
    gemm_tc<true , false, false, false><<<gDD, 256, GEMM_SMEM>>>(h, W_k, nullptr, nullptr, k, MROWS, DDIM, DDIM);
    gemm_tc<true , false, false, false><<<gDD, 256, GEMM_SMEM>>>(h, W_v, nullptr, nullptr, v, MROWS, DDIM, DDIM);
    attn_kernel<<<dim3(LL / 64, BB * HH), 256>>>(q, k, v, ctx);
    gemm_tc<true , false, false, true ><<<gDD, 256, GEMM_SMEM>>>(ctx, W_o, nullptr, x, x1, MROWS, DDIM, DDIM);
    ln_kernel<<<MROWS, 256>>>(x1, ln2_g, ln2_b, h);
    gemm_tc<false, true , true , false><<<gFF, 256, GEMM_SMEM>>>(h, fc1_W, fc1_b, nullptr, f, MROWS, DFFN, DDIM);
    gemm_tc<false, false, true , true ><<<gDD, 256, GEMM_SMEM>>>(f, fc2_W, fc2_b, x1, out, MROWS, DDIM, DFFN);
}

// round 7
// speedup vs baseline: 3.1841x; 1.3788x over previous
#include <cuda_runtime.h>
#include <math.h>
#include <stdint.h>

// Problem dims (fixed)
#define BB   2
#define LL   2048
#define DDIM 1024
#define HH   16
#define DHD  64
#define DFFN 4096
#define MROWS (BB*LL)   // 4096 token rows

// ---------------------------------------------------------------------------
// Scratch (device globals; no runtime allocation allowed)
// ---------------------------------------------------------------------------
__device__ float g_h  [(size_t)MROWS * DDIM];
__device__ float g_q  [(size_t)MROWS * DDIM];
__device__ float g_k  [(size_t)MROWS * DDIM];
__device__ float g_v  [(size_t)MROWS * DDIM];
__device__ float g_ctx[(size_t)MROWS * DDIM];
__device__ float g_x1 [(size_t)MROWS * DDIM];
__device__ float g_f  [(size_t)MROWS * DFFN];
// tf32-rounded weight copies
__device__ float g_wq [(size_t)DDIM * DDIM];
__device__ float g_wk [(size_t)DDIM * DDIM];
__device__ float g_wv [(size_t)DDIM * DDIM];
__device__ float g_wo [(size_t)DDIM * DDIM];
__device__ float g_w1 [(size_t)DDIM * DFFN];
__device__ float g_w2 [(size_t)DFFN * DDIM];

// ---------------------------------------------------------------------------
// PTX helpers
// ---------------------------------------------------------------------------
__device__ __forceinline__ uint32_t smem_u32(const void* p) {
    return (uint32_t)__cvta_generic_to_shared(p);
}
__device__ __forceinline__ void cp_async16(uint32_t dst, const void* src) {
    asm volatile("cp.async.cg.shared.global [%0], [%1], 16;" :: "r"(dst), "l"(src));
}
__device__ __forceinline__ void cp_commit() {
    asm volatile("cp.async.commit_group;");
}
template<int N>
__device__ __forceinline__ void cp_wait() {
    asm volatile("cp.async.wait_group %0;" :: "n"(N));
}
__device__ __forceinline__ float rna(float f) {
    uint32_t r;
    asm("cvt.rna.tf32.f32 %0, %1;" : "=r"(r) : "f"(f));
    return __uint_as_float(r);
}
__device__ __forceinline__ void mma_tf32(float* c, const uint32_t* a, const uint32_t* b) {
    asm volatile(
        "mma.sync.aligned.m16n8k8.row.col.f32.tf32.tf32.f32 "
        "{%0,%1,%2,%3},{%4,%5,%6,%7},{%8,%9},{%0,%1,%2,%3};"
        : "+f"(c[0]), "+f"(c[1]), "+f"(c[2]), "+f"(c[3])
        : "r"(a[0]), "r"(a[1]), "r"(a[2]), "r"(a[3]), "r"(b[0]), "r"(b[1]));
}
__device__ __forceinline__ void ldsm_x4(uint32_t* r, uint32_t addr) {
    asm volatile("ldmatrix.sync.aligned.m8n8.x4.shared.b16 {%0,%1,%2,%3}, [%4];"
        : "=r"(r[0]), "=r"(r[1]), "=r"(r[2]), "=r"(r[3]) : "r"(addr));
}
__device__ __forceinline__ void ldsm_x2(uint32_t* r, uint32_t addr) {
    asm volatile("ldmatrix.sync.aligned.m8n8.x2.shared.b16 {%0,%1}, [%2];"
        : "=r"(r[0]), "=r"(r[1]) : "r"(addr));
}

// ---------------------------------------------------------------------------
// Round fp32 -> tf32 (rna) elementwise, float4 per thread
// ---------------------------------------------------------------------------
__global__ void __launch_bounds__(256) round_kernel(const float* __restrict__ in,
                                                    float* __restrict__ out, int n4) {
    int i = blockIdx.x * 256 + threadIdx.x;
    if (i < n4) {
        float4 v = ((const float4*)in)[i];
        v.x = rna(v.x); v.y = rna(v.y); v.z = rna(v.z); v.w = rna(v.w);
        ((float4*)out)[i] = v;
    }
}

// ---------------------------------------------------------------------------
// LayerNorm; optionally rounds output to tf32 (when it feeds a GEMM A operand)
// ---------------------------------------------------------------------------
template<bool RND>
__global__ void __launch_bounds__(256) ln_kernel(const float* __restrict__ x,
                                                 const float* __restrict__ g,
                                                 const float* __restrict__ b,
                                                 float* __restrict__ out) {
    int row = blockIdx.x;
    int t = threadIdx.x;
    const float4* xr = (const float4*)(x + (size_t)row * DDIM);
    float4 v = xr[t];
    __shared__ float sred[8];

    float s = v.x + v.y + v.z + v.w;
    #pragma unroll
    for (int o = 16; o > 0; o >>= 1) s += __shfl_xor_sync(0xffffffffu, s, o);
    if ((t & 31) == 0) sred[t >> 5] = s;
    __syncthreads();
    float tot = 0.f;
    #pragma unroll
    for (int w = 0; w < 8; w++) tot += sred[w];
    float mu = tot * (1.0f / DDIM);

    float dx = v.x - mu, dy = v.y - mu, dz = v.z - mu, dw = v.w - mu;
    float s2 = dx*dx + dy*dy + dz*dz + dw*dw;
    #pragma unroll
    for (int o = 16; o > 0; o >>= 1) s2 += __shfl_xor_sync(0xffffffffu, s2, o);
    __syncthreads();
    if ((t & 31) == 0) sred[t >> 5] = s2;
    __syncthreads();
    float tv = 0.f;
    #pragma unroll
    for (int w = 0; w < 8; w++) tv += sred[w];
    float rstd = rsqrtf(tv * (1.0f / DDIM) + 1e-5f);

    float4 gg = ((const float4*)g)[t];
    float4 bb = ((const float4*)b)[t];
    float4 o4;
    o4.x = dx * rstd * gg.x + bb.x;
    o4.y = dy * rstd * gg.y + bb.y;
    o4.z = dz * rstd * gg.z + bb.z;
    o4.w = dw * rstd * gg.w + bb.w;
    if (RND) { o4.x = rna(o4.x); o4.y = rna(o4.y); o4.z = rna(o4.z); o4.w = rna(o4.w); }
    ((float4*)(out + (size_t)row * DDIM))[t] = o4;
}

// ---------------------------------------------------------------------------
// tf32 tensor-core GEMM: C[M,N] = A[M,K] @ (TB ? B[N,K]^T : B[K,N])
// All GEMM inputs are pre-rounded to tf32 -> raw-bit MMA operands are exact.
// CTA 128x128x16, 8 warps (2x4), warp 64x32, mma.m16n8k8.
// 3-stage cp.async ring, one __syncthreads per k-tile.
// Fragment loads: ldmatrix x4 (A), ldmatrix x2 (B, NT); scalar LDS (B, NN).
// RND: round outputs to tf32 (when C feeds a later GEMM/MMA as operand).
// ---------------------------------------------------------------------------
#define BMT 128
#define BNT 128
#define BKT 16
#define NSTG 3
#define STG_F 2560
#define GEMM_SMEM (NSTG * STG_F * 2 * 4)

template<bool TB, bool GELU, bool BIAS, bool RES, bool RND>
__global__ void __launch_bounds__(256) gemm_tc(
    const float* __restrict__ A, const float* __restrict__ Bm,
    const float* __restrict__ bias, const float* __restrict__ res,
    float* __restrict__ C, int M, int N, int K)
{
    extern __shared__ float sm[];
    float* As = sm;                  // [NSTG][2560]  ([row][k] stride 20)
    float* Bs = sm + NSTG * STG_F;   // NT: [n][k] s20; NN: [k][n] s136

    int tid  = threadIdx.x;
    int lane = tid & 31;
    int wid  = tid >> 5;
    int wm   = wid >> 2;
    int wn   = wid & 3;
    int m0 = blockIdx.y * BMT;
    int n0 = blockIdx.x * BNT;

    float acc[4][4][4];
    #pragma unroll
    for (int i = 0; i < 4; i++)
        #pragma unroll
        for (int j = 0; j < 4; j++)
            #pragma unroll
            for (int r = 0; r < 4; r++) acc[i][j][r] = 0.f;

    auto issue = [&](int st, int k0) {
        float* as = As + st * STG_F;
        float* bs = Bs + st * STG_F;
        #pragma unroll
        for (int i = 0; i < 2; i++) {
            int idx = tid + i * 256;
            int row = idx >> 2, c = idx & 3;
            cp_async16(smem_u32(as + row * 20 + c * 4),
                       A + (size_t)(m0 + row) * K + k0 + c * 4);
        }
        if (TB) {
            #pragma unroll
            for (int i = 0; i < 2; i++) {
                int idx = tid + i * 256;
                int row = idx >> 2, c = idx & 3;
                cp_async16(smem_u32(bs + row * 20 + c * 4),
                           Bm + (size_t)(n0 + row) * K + k0 + c * 4);
            }
        } else {
            #pragma unroll
            for (int i = 0; i < 2; i++) {
                int idx = tid + i * 256;
                int k = idx >> 5, n4 = idx & 31;
                cp_async16(smem_u32(bs + k * 136 + n4 * 4),
                           Bm + (size_t)(k0 + k) * N + n0 + n4 * 4);
            }
        }
        cp_commit();
    };

    int nk = K / BKT;
    issue(0, 0);
    issue(1, BKT);

    for (int kt = 0; kt < nk; kt++) {
        if (kt + 1 < nk) cp_wait<1>(); else cp_wait<0>();
        __syncthreads();

        if (kt + 2 < nk) issue((kt + 2) % NSTG, (kt + 2) * BKT);

        const float* as = As + (kt % NSTG) * STG_F;
        const float* bs = Bs + (kt % NSTG) * STG_F;
        #pragma unroll
        for (int ks = 0; ks < 2; ks++) {
            uint32_t af[4][4], bf[4][2];
            // A fragments via ldmatrix.x4
            {
                int rowbase = wm * 64 + (lane & 15);
                int koff = ks * 8 + ((lane >> 4) << 2);
                #pragma unroll
                for (int mt = 0; mt < 4; mt++)
                    ldsm_x4(af[mt], smem_u32(as + (rowbase + mt * 16) * 20 + koff));
            }
            if (TB) {
                int nb = wn * 32 + (lane & 7);
                int koff = ks * 8 + ((lane & 8) ? 4 : 0);
                #pragma unroll
                for (int nt = 0; nt < 4; nt++)
                    ldsm_x2(bf[nt], smem_u32(bs + (nb + nt * 8) * 20 + koff));
            } else {
                int ak = ks * 8 + (lane & 3);
                #pragma unroll
                for (int nt = 0; nt < 4; nt++) {
                    int bn = wn * 32 + nt * 8 + (lane >> 2);
                    bf[nt][0] = __float_as_uint(bs[(ak    ) * 136 + bn]);
                    bf[nt][1] = __float_as_uint(bs[(ak + 4) * 136 + bn]);
                }
            }
            #pragma unroll
            for (int mt = 0; mt < 4; mt++)
                #pragma unroll
                for (int nt = 0; nt < 4; nt++)
                    mma_tf32(acc[mt][nt], af[mt], bf[nt]);
        }
    }

    // ---- epilogue ----
    #pragma unroll
    for (int mt = 0; mt < 4; mt++) {
        #pragma unroll
        for (int nt = 0; nt < 4; nt++) {
            int row = m0 + wm * 64 + mt * 16 + (lane >> 2);
            int col = n0 + wn * 32 + nt * 8 + (lane & 3) * 2;
            #pragma unroll
            for (int half = 0; half < 2; half++) {
                int r = row + half * 8;
                float v0 = acc[mt][nt][half * 2 + 0];
                float v1 = acc[mt][nt][half * 2 + 1];
                if (BIAS) { v0 += bias[col]; v1 += bias[col + 1]; }
                if (GELU) {
                    v0 = 0.5f * v0 * (1.0f + erff(v0 * 0.70710678118654752f));
                    v1 = 0.5f * v1 * (1.0f + erff(v1 * 0.70710678118654752f));
                }
                if (RES) {
                    const float2 rr = *(const float2*)(res + (size_t)r * N + col);
                    v0 += rr.x; v1 += rr.y;
                }
                if (RND) { v0 = rna(v0); v1 = rna(v1); }
                float2 o2; o2.x = v0; o2.y = v1;
                *(float2*)(C + (size_t)r * N + col) = o2;
            }
        }
    }
}

// ---------------------------------------------------------------------------
// Causal flash attention with tf32 tensor cores.
// Block: 256 threads (8 warps), q-tile 64 rows, kv-tile 32, per (b,h).
// S = Q K^T via mma -> smem Ps -> scalar online softmax (4 thr/row) ->
// O += P V via mma. Q,K,V pre-rounded tf32; P rounded in softmax.
// Warp w: row band mi = w&3 (16 rows).
//   S: cols (w>>2)*16 + {0,8}   (2 n8 tiles)
//   O: cols (w>>2)*32 + {0,8,16,24} (4 n8 tiles)
// ---------------------------------------------------------------------------
__global__ void __launch_bounds__(256) attn_kernel(
    const float* __restrict__ Q, const float* __restrict__ K,
    const float* __restrict__ V, float* __restrict__ O) {
    __shared__ float Qs[64][68];    // [r][d]
    __shared__ float Ks[32][68];    // [c][d]
    __shared__ float Vs[64][44];    // [d][c]
    __shared__ float Ps[64][36];    // [r][c]
    __shared__ float sm_m[64], sm_l[64], sm_fc[64];

    int tid  = threadIdx.x;
    int lane = tid & 31;
    int wid  = tid >> 5;
    int mi   = wid & 3;
    int whalf = wid >> 2;           // 0..1
    int qt = blockIdx.x;
    int bh = blockIdx.y;
    size_t base = (size_t)(bh / HH) * LL * DDIM + (size_t)(bh % HH) * DHD;
    int q0 = qt * 64;

    // Load Q tile [64][64] (float4, coalesced)
    #pragma unroll
    for (int i = 0; i < 4; i++) {
        int e = tid + i * 256;          // 0..1023
        int r = e >> 4, c4 = (e & 15) * 4;
        *(float4*)&Qs[r][c4] = *(const float4*)(Q + base + (size_t)(q0 + r) * DDIM + c4);
    }
    if (tid < 64) { sm_m[tid] = -3.0e38f; sm_l[tid] = 0.f; }

    float o[4][4];
    #pragma unroll
    for (int nt = 0; nt < 4; nt++)
        #pragma unroll
        for (int r = 0; r < 4; r++) o[nt][r] = 0.f;

    int r0 = mi * 16 + (lane >> 2);     // softmax-fragment rows
    int r1 = r0 + 8;

    int nkt = (q0 + 64) / 32;
    for (int kt = 0; kt < nkt; kt++) {
        int k0 = kt * 32;
        __syncthreads();    // previous PV done; safe to overwrite Ks/Vs
        // K: [32][64] direct (float4)
        #pragma unroll
        for (int i = 0; i < 2; i++) {
            int e = tid + i * 256;      // 0..511
            int c = e >> 4, d4 = (e & 15) * 4;
            *(float4*)&Ks[c][d4] = *(const float4*)(K + base + (size_t)(k0 + c) * DDIM + d4);
        }
        // V: transpose into Vs[d][c]
        #pragma unroll
        for (int i = 0; i < 8; i++) {
            int e = tid + i * 256;      // 0..2047
            int c = e >> 6, d = e & 63;
            Vs[d][c] = V[base + (size_t)(k0 + c) * DDIM + d];
        }
        __syncthreads();

        // ---- S = Q K^T (64x32), warp computes 16x16 ----
        float cs[2][4];
        #pragma unroll
        for (int nt = 0; nt < 2; nt++)
            #pragma unroll
            for (int r = 0; r < 4; r++) cs[nt][r] = 0.f;
        #pragma unroll
        for (int ks = 0; ks < 8; ks++) {
            uint32_t aq[4], bk[2][2];
            int rowQ = mi * 16 + (lane & 15);
            int koff = ks * 8 + ((lane >> 4) << 2);
            ldsm_x4(aq, smem_u32(&Qs[rowQ][0] + koff));
            int nb = whalf * 16 + (lane & 7);
            int koffb = ks * 8 + ((lane & 8) ? 4 : 0);
            ldsm_x2(bk[0], smem_u32(&Ks[nb][0] + koffb));
            ldsm_x2(bk[1], smem_u32(&Ks[nb + 8][0] + koffb));
            mma_tf32(cs[0], aq, bk[0]);
            mma_tf32(cs[1], aq, bk[1]);
        }
        // scale, mask, store S to Ps
        {
            int cb = whalf * 16 + (lane & 3) * 2;
            #pragma unroll
            for (int nt = 0; nt < 2; nt++) {
                int c0 = cb + nt * 8;
                float s00 = cs[nt][0] * 0.125f, s01 = cs[nt][1] * 0.125f;
                float s10 = cs[nt][2] * 0.125f, s11 = cs[nt][3] * 0.125f;
                if (k0 + c0     > q0 + r0) s00 = -3.0e38f;
                if (k0 + c0 + 1 > q0 + r0) s01 = -3.0e38f;
                if (k0 + c0     > q0 + r1) s10 = -3.0e38f;
                if (k0 + c0 + 1 > q0 + r1) s11 = -3.0e38f;
                float2 t0; t0.x = s00; t0.y = s01;
                float2 t1; t1.x = s10; t1.y = s11;
                *(float2*)&Ps[r0][c0] = t0;
                *(float2*)&Ps[r1][c0] = t1;
            }
        }
        __syncthreads();

        // ---- online softmax: 4 threads per row, 8 cols each ----
        {
            int row = tid >> 2;
            int qd  = tid & 3;
            float sv[8];
            #pragma unroll
            for (int j = 0; j < 8; j++) sv[j] = Ps[row][qd * 8 + j];
            float tmax = sv[0];
            #pragma unroll
            for (int j = 1; j < 8; j++) tmax = fmaxf(tmax, sv[j]);
            tmax = fmaxf(tmax, __shfl_xor_sync(0xffffffffu, tmax, 1));
            tmax = fmaxf(tmax, __shfl_xor_sync(0xffffffffu, tmax, 2));
            float mold = sm_m[row];
            float newm = fmaxf(mold, tmax);
            float fcr  = __expf(mold - newm);
            float tsum = 0.f;
            #pragma unroll
            for (int j = 0; j < 8; j++) {
                float p = __expf(sv[j] - newm);
                tsum += p;
                sv[j] = rna(p);          // round P for tf32 MMA
            }
            #pragma unroll
            for (int j = 0; j < 8; j++) Ps[row][qd * 8 + j] = sv[j];
            tsum += __shfl_xor_sync(0xffffffffu, tsum, 1);
            tsum += __shfl_xor_sync(0xffffffffu, tsum, 2);
            if (qd == 0) {
                sm_m[row]  = newm;
                sm_l[row]  = sm_l[row] * fcr + tsum;
                sm_fc[row] = fcr;
            }
        }
        __syncthreads();

        // ---- O = O*fc + P V  (warp: 16 rows x 32 cols) ----
        {
            float f0 = sm_fc[r0], f1 = sm_fc[r1];
            #pragma unroll
            for (int nt = 0; nt < 4; nt++) {
                o[nt][0] *= f0; o[nt][1] *= f0;
                o[nt][2] *= f1; o[nt][3] *= f1;
            }
            #pragma unroll
            for (int ks = 0; ks < 4; ks++) {
                uint32_t ap[4], bv[4][2];
                int rowP = mi * 16 + (lane & 15);
                int koff = ks * 8 + ((lane >> 4) << 2);
                ldsm_x4(ap, smem_u32(&Ps[rowP][0] + koff));
                int nb = whalf * 32 + (lane & 7);
                int koffb = ks * 8 + ((lane & 8) ? 4 : 0);
                #pragma unroll
                for (int nt = 0; nt < 4; nt++)
                    ldsm_x2(bv[nt], smem_u32(&Vs[nb + nt * 8][0] + koffb));
                #pragma unroll
                for (int nt = 0; nt < 4; nt++)
                    mma_tf32(o[nt], ap, bv[nt]);
            }
        }
    }

    __syncthreads();
    // epilogue: divide by l, round (ctx feeds W_o GEMM), store
    {
        float inv0 = 1.0f / sm_l[r0];
        float inv1 = 1.0f / sm_l[r1];
        #pragma unroll
        for (int nt = 0; nt < 4; nt++) {
            int col = whalf * 32 + nt * 8 + (lane & 3) * 2;
            float2 t0, t1;
            t0.x = rna(o[nt][0] * inv0); t0.y = rna(o[nt][1] * inv0);
            t1.x = rna(o[nt][2] * inv1); t1.y = rna(o[nt][3] * inv1);
            *(float2*)(O + base + (size_t)(q0 + r0) * DDIM + col) = t0;
            *(float2*)(O + base + (size_t)(q0 + r1) * DDIM + col) = t1;
        }
    }
}

// ---------------------------------------------------------------------------
// Launch sequence
// ---------------------------------------------------------------------------
extern "C" void kernel_launch(void* const* d_in, const int* in_sizes, int n_in,
                              void* d_out, int out_size) {
    const float* x     = (const float*)d_in[0];
    const float* ln1_g = (const float*)d_in[2];
    const float* ln1_b = (const float*)d_in[3];
    const float* W_q   = (const float*)d_in[4];
    const float* W_k   = (const float*)d_in[5];
    const float* W_v   = (const float*)d_in[6];
    const float* W_o   = (const float*)d_in[7];
    const float* ln2_g = (const float*)d_in[8];
    const float* ln2_b = (const float*)d_in[9];
    const float* fc1_W = (const float*)d_in[10];
    const float* fc1_b = (const float*)d_in[11];
    const float* fc2_W = (const float*)d_in[12];
    const float* fc2_b = (const float*)d_in[13];
    float* out = (float*)d_out;

    float *h, *q, *k, *v, *ctx, *x1, *f;
    float *wq, *wk, *wv, *wo, *w1, *w2;
    cudaGetSymbolAddress((void**)&h,   g_h);
    cudaGetSymbolAddress((void**)&q,   g_q);
    cudaGetSymbolAddress((void**)&k,   g_k);
    cudaGetSymbolAddress((void**)&v,   g_v);
    cudaGetSymbolAddress((void**)&ctx, g_ctx);
    cudaGetSymbolAddress((void**)&x1,  g_x1);
    cudaGetSymbolAddress((void**)&f,   g_f);
    cudaGetSymbolAddress((void**)&wq,  g_wq);
    cudaGetSymbolAddress((void**)&wk,  g_wk);
    cudaGetSymbolAddress((void**)&wv,  g_wv);
    cudaGetSymbolAddress((void**)&wo,  g_wo);
    cudaGetSymbolAddress((void**)&w1,  g_w1);
    cudaGetSymbolAddress((void**)&w2,  g_w2);

    cudaFuncSetAttribute(gemm_tc<true , false, false, false, true >, cudaFuncAttributeMaxDynamicSharedMemorySize, GEMM_SMEM);
    cudaFuncSetAttribute(gemm_tc<true , false, false, true , false>, cudaFuncAttributeMaxDynamicSharedMemorySize, GEMM_SMEM);
    cudaFuncSetAttribute(gemm_tc<false, true , true , false, true >, cudaFuncAttributeMaxDynamicSharedMemorySize, GEMM_SMEM);
    cudaFuncSetAttribute(gemm_tc<false, false, true , true , false>, cudaFuncAttributeMaxDynamicSharedMemorySize, GEMM_SMEM);

    // 0) round weights to tf32 (once per launch; cheap, DRAM-bound)
    int nDD = DDIM * DDIM / 4, nDF = DDIM * DFFN / 4;
    round_kernel<<<(nDD + 255) / 256, 256>>>(W_q,   wq, nDD);
    round_kernel<<<(nDD + 255) / 256, 256>>>(W_k,   wk, nDD);
    round_kernel<<<(nDD + 255) / 256, 256>>>(W_v,   wv, nDD);
    round_kernel<<<(nDD + 255) / 256, 256>>>(W_o,   wo, nDD);
    round_kernel<<<(nDF + 255) / 256, 256>>>(fc1_W, w1, nDF);
    round_kernel<<<(nDF + 255) / 256, 256>>>(fc2_W, w2, nDF);

    dim3 gDD(DDIM / BNT, MROWS / BMT);     // (8, 32)
    dim3 gFF(DFFN / BNT, MROWS / BMT);     // (32, 32)

    // 1) h = round(LN1(x))
    ln_kernel<true><<<MROWS, 256>>>(x, ln1_g, ln1_b, h);
    // 2) q,k,v = round(h @ W^T)
    gemm_tc<true , false, false, false, true ><<<gDD, 256, GEMM_SMEM>>>(h, wq, nullptr, nullptr, q, MROWS, DDIM, DDIM);
    gemm_tc<true , false, false, false, true ><<<gDD, 256, GEMM_SMEM>>>(h, wk, nullptr, nullptr, k, MROWS, DDIM, DDIM);
    gemm_tc<true , false, false, false, true ><<<gDD, 256, GEMM_SMEM>>>(h, wv, nullptr, nullptr, v, MROWS, DDIM, DDIM);
    // 3) ctx = round(causal-softmax(q k^T / 8) v)
    attn_kernel<<<dim3(LL / 64, BB * HH), 256>>>(q, k, v, ctx);
    // 4) x1 = x + ctx @ W_o^T (exact fp32 residual)
    gemm_tc<true , false, false, true , false><<<gDD, 256, GEMM_SMEM>>>(ctx, wo, nullptr, x, x1, MROWS, DDIM, DDIM);
    // 5) h = round(LN2(x1))
    ln_kernel<true><<<MROWS, 256>>>(x1, ln2_g, ln2_b, h);
    // 6) f = round(gelu(h @ fc1_W + b))
    gemm_tc<false, true , true , false, true ><<<gFF, 256, GEMM_SMEM>>>(h, w1, fc1_b, nullptr, f, MROWS, DFFN, DDIM);
    // 7) out = x1 + f @ fc2_W + b
    gemm_tc<false, false, true , true , false><<<gDD, 256, GEMM_SMEM>>>(f, w2, fc2_b, x1, out, MROWS, DDIM, DFFN);
}